// round 5
// baseline (speedup 1.0000x reference)
#include <cuda_runtime.h>
#include <cstdint>

typedef unsigned long long ull;

#define SEQ    512
#define BATCH  128
#define INPUT  128
#define HIDDEN 512
#define CLUSTER 8
#define THREADS 512

// ---- smem layout (bytes) ----
#define WS_OFF   0                         // W slice [512 k][64 n] fp32
#define HC_OFF   131072                    // compact relu(h) [2][512 k][8 b] fp32
#define HD_OFF   163840                    // dup relu(h) [512 k][8 b] f32x2 (8B)
#define SCR_OFF  196608                    // partials [8 kq][8 b][64 n] fp32
#define SMEM_BYTES (196608 + 16384)        // 212992

// ---------------------------------------------------------------------------
// Phase 1: proj[row,n] = sum_k input[row,k] * W_in[n,k] -> d_out
// ---------------------------------------------------------------------------
__global__ __launch_bounds__(256) void proj_kernel(
    const float* __restrict__ A, const float* __restrict__ W,
    float* __restrict__ C)
{
    __shared__ float As[64][65];
    __shared__ float Bs[64][65];
    const int tid = threadIdx.x, tx = tid & 15, ty = tid >> 4;
    const int row0 = blockIdx.x * 64, n0 = blockIdx.y * 64;
    float acc[4][4] = {};
    for (int k0 = 0; k0 < INPUT; k0 += 64) {
        #pragma unroll
        for (int i = 0; i < 16; i++) {
            int e = tid + i * 256, r = e >> 6, kk = e & 63;
            As[kk][r] = A[(row0 + r) * INPUT + k0 + kk];
            Bs[kk][r] = W[(n0 + r) * INPUT + k0 + kk];
        }
        __syncthreads();
        #pragma unroll 8
        for (int k = 0; k < 64; k++) {
            float a[4], b[4];
            #pragma unroll
            for (int i = 0; i < 4; i++) a[i] = As[k][ty * 4 + i];
            #pragma unroll
            for (int j = 0; j < 4; j++) b[j] = Bs[k][tx * 4 + j];
            #pragma unroll
            for (int i = 0; i < 4; i++)
                #pragma unroll
                for (int j = 0; j < 4; j++) acc[i][j] += a[i] * b[j];
        }
        __syncthreads();
    }
    #pragma unroll
    for (int i = 0; i < 4; i++) {
        int row = row0 + ty * 4 + i;
        #pragma unroll
        for (int j = 0; j < 4; j++)
            C[row * HIDDEN + n0 + tx * 4 + j] = acc[i][j];
    }
}

// ---- packed fp32 helpers ----------------------------------------------------
__device__ __forceinline__ void fma2(ull& d, ull a, ull b) {
    asm("fma.rn.f32x2 %0, %1, %2, %0;" : "+l"(d) : "l"(a), "l"(b));
}
__device__ __forceinline__ ull fma2r(ull a, ull b, ull c) {
    ull d; asm("fma.rn.f32x2 %0, %1, %2, %3;" : "=l"(d) : "l"(a), "l"(b), "l"(c)); return d;
}
__device__ __forceinline__ ull add2(ull a, ull b) {
    ull d; asm("add.rn.f32x2 %0, %1, %2;" : "=l"(d) : "l"(a), "l"(b)); return d;
}
__device__ __forceinline__ ull mul2(ull a, ull b) {
    ull d; asm("mul.rn.f32x2 %0, %1, %2;" : "=l"(d) : "l"(a), "l"(b)); return d;
}
__device__ __forceinline__ ull pk(float lo, float hi) {
    ull d; asm("mov.b64 %0, {%1, %2};" : "=l"(d) : "f"(lo), "f"(hi)); return d;
}
__device__ __forceinline__ void upk(float& lo, float& hi, ull v) {
    asm("mov.b64 {%0, %1}, %2;" : "=f"(lo), "=f"(hi) : "l"(v));
}
__device__ __forceinline__ uint32_t s2u(const void* p) {
    uint32_t a;
    asm("{ .reg .u64 t; cvta.to.shared.u64 t, %1; cvt.u32.u64 %0, t; }" : "=r"(a) : "l"(p));
    return a;
}

// ---------------------------------------------------------------------------
// Phase 2: persistent cluster recurrence. 16 clusters x 8 CTAs, 512 thr/CTA.
//   rank r owns hidden cols [64r,64r+64); cluster owns 8 batch rows.
//   matvec: f32x2, 8-way k-split, thread tile 2b x 4n over 64 k.
// ---------------------------------------------------------------------------
__global__ void __launch_bounds__(THREADS, 1) __cluster_dims__(CLUSTER, 1, 1)
recurrent_kernel(const float* __restrict__ Whid,
                 const float* __restrict__ noise,
                 float* __restrict__ out, int has_tail)
{
    extern __shared__ float sm[];
    const uint32_t sbase = s2u(sm);
    const uint32_t sW   = sbase + WS_OFF;
    const uint32_t sHC  = sbase + HC_OFF;
    const uint32_t sHD  = sbase + HD_OFF;
    const uint32_t sSCR = sbase + SCR_OFF;

    const int tid = threadIdx.x;
    uint32_t rank;
    asm("mov.u32 %0, %%cluster_ctarank;" : "=r"(rank));
    const int n0r   = (int)rank * 64;
    const int bbase = (blockIdx.x >> 3) * 8;

    // ---- load W slice transposed: Ws[k*64+n] = Whid[n0r+n][k] ----
    for (int e = tid; e < 64 * 128; e += THREADS) {
        int n = e >> 7, kq4 = e & 127;
        float4 v = reinterpret_cast<const float4*>(Whid)[(n0r + n) * 128 + kq4];
        float* w = sm + (WS_OFF / 4);
        w[(4 * kq4 + 0) * 64 + n] = v.x;
        w[(4 * kq4 + 1) * 64 + n] = v.y;
        w[(4 * kq4 + 2) * 64 + n] = v.z;
        w[(4 * kq4 + 3) * 64 + n] = v.w;
    }
    // ---- zero compact h buffers (h0 = 0) ----
    for (int e = tid; e < 2 * 512 * 8; e += THREADS)
        sm[HC_OFF / 4 + e] = 0.0f;

    // ---- peer base addresses ----
    uint32_t peer[CLUSTER];
    #pragma unroll
    for (int r = 0; r < CLUSTER; r++)
        asm("mapa.shared::cluster.u32 %0, %1, %2;"
            : "=r"(peer[r]) : "r"(sbase), "r"(r));

    __syncthreads();
    asm volatile("barrier.cluster.arrive.aligned;" ::: "memory");
    asm volatile("barrier.cluster.wait.aligned;"   ::: "memory");

    // matvec mapping: kq = tid>>6 (8 k-slices of 64), u = tid&63: ng,bg
    const int kq = tid >> 6;
    const int ng = tid & 15;           // n = 4*ng
    const int bg = (tid >> 4) & 3;     // b = {2bg, 2bg+1}
    const uint32_t wp0 = sW  + (kq * 64 * 64 + 4 * ng) * 4;
    const uint32_t hp0 = sHD + (kq * 64 * 8 + 2 * bg) * 8;
    const uint32_t sc0 = sSCR + (kq * 512 + 2 * bg * 64 + 4 * ng) * 4;

    // epilogue mapping (low 256 threads): output pair (b, col..col+1)
    const int eb   = tid >> 5;                 // 0..7
    const int ecol = n0r + 2 * (tid & 31);     // even col
    const ull half2 = pk(0.5f, 0.5f);
    ull rh = 0;                                // raw h pair, lives all steps
    int pp = 0;

    for (int s = 0; s < SEQ; s++) {
        // ---- dup pass: hd[k][b] = (hc[pp][k][b], same) ----
        {
            uint32_t src = sHC + pp * 16384 + tid * 32;   // 8 floats of row k=tid
            uint32_t dst = sHD + tid * 64;
            float4 v0, v1;
            asm("ld.shared.v4.f32 {%0,%1,%2,%3}, [%4];"
                : "=f"(v0.x), "=f"(v0.y), "=f"(v0.z), "=f"(v0.w) : "r"(src));
            asm("ld.shared.v4.f32 {%0,%1,%2,%3}, [%4];"
                : "=f"(v1.x), "=f"(v1.y), "=f"(v1.z), "=f"(v1.w) : "r"(src + 16));
            ull d0 = pk(v0.x, v0.x), d1 = pk(v0.y, v0.y);
            ull d2 = pk(v0.z, v0.z), d3 = pk(v0.w, v0.w);
            ull d4 = pk(v1.x, v1.x), d5 = pk(v1.y, v1.y);
            ull d6 = pk(v1.z, v1.z), d7 = pk(v1.w, v1.w);
            asm volatile("st.shared.v2.u64 [%0],    {%1,%2};" :: "r"(dst), "l"(d0), "l"(d1));
            asm volatile("st.shared.v2.u64 [%0+16], {%1,%2};" :: "r"(dst), "l"(d2), "l"(d3));
            asm volatile("st.shared.v2.u64 [%0+32], {%1,%2};" :: "r"(dst), "l"(d4), "l"(d5));
            asm volatile("st.shared.v2.u64 [%0+48], {%1,%2};" :: "r"(dst), "l"(d6), "l"(d7));
        }
        __syncthreads();

        // ---- prefetch globals for epilogue (low threads) ----
        ull x2 = 0, nz2 = 0;
        float* optr = out + ((size_t)s * BATCH + bbase + eb) * HIDDEN + ecol;
        if (tid < 256) {
            float2 xv = *reinterpret_cast<const float2*>(optr);
            float2 nv = *reinterpret_cast<const float2*>(noise + (size_t)s * HIDDEN + ecol);
            x2  = pk(xv.x, xv.y);
            nz2 = pk(nv.x, nv.y);
        }

        // ---- matvec over this thread's 64-k slice ----
        ull a00 = 0, a01 = 0, a10 = 0, a11 = 0;
        #pragma unroll 8
        for (int k = 0; k < 64; k++) {
            ull w01, w23, h0, h1;
            asm("ld.shared.v2.u64 {%0,%1}, [%2];"
                : "=l"(w01), "=l"(w23) : "r"(wp0 + k * 256));
            asm("ld.shared.v2.u64 {%0,%1}, [%2];"
                : "=l"(h0), "=l"(h1) : "r"(hp0 + k * 64));
            fma2(a00, h0, w01); fma2(a01, h0, w23);
            fma2(a10, h1, w01); fma2(a11, h1, w23);
        }
        asm volatile("st.shared.v2.u64 [%0],     {%1,%2};" :: "r"(sc0), "l"(a00), "l"(a01));
        asm volatile("st.shared.v2.u64 [%0+256], {%1,%2};" :: "r"(sc0), "l"(a10), "l"(a11));
        __syncthreads();

        // ---- reduce partials + state update + exchange (low 256 threads) ----
        if (tid < 256) {
            uint32_t rp = sSCR + (eb * 64 + (ecol - n0r)) * 4;
            ull acc = 0;
            #pragma unroll
            for (int q = 0; q < 8; q++) {
                ull v; asm("ld.shared.u64 %0, [%1];" : "=l"(v) : "r"(rp + q * 2048));
                acc = add2(acc, v);
            }
            ull t   = add2(acc, add2(x2, nz2));
            ull hn  = fma2r(rh, half2, mul2(t, half2));   // 0.5*rh + 0.5*t
            rh = hn;
            float h0, h1; upk(h0, h1, hn);
            *reinterpret_cast<float2*>(optr) = make_float2(h0, h1);
            float r0 = fmaxf(h0, 0.0f), r1 = fmaxf(h1, 0.0f);

            uint32_t off0 = (uint32_t)(HC_OFF + (pp ^ 1) * 16384 + (ecol * 8 + eb) * 4);
            #pragma unroll
            for (int r = 0; r < CLUSTER; r++) {
                asm volatile("st.shared::cluster.f32 [%0], %1;"
                             :: "r"(peer[r] + off0), "f"(r0) : "memory");
                asm volatile("st.shared::cluster.f32 [%0], %1;"
                             :: "r"(peer[r] + off0 + 32), "f"(r1) : "memory");
            }
        }
        asm volatile("barrier.cluster.arrive.aligned;" ::: "memory");
        asm volatile("barrier.cluster.wait.aligned;"   ::: "memory");
        pp ^= 1;
    }

    // ---- fused tail: final hidden state ----
    if (has_tail && tid < 256) {
        float h0, h1; upk(h0, h1, rh);
        float* tp = out + (size_t)SEQ * BATCH * HIDDEN
                        + (size_t)(bbase + eb) * HIDDEN + ecol;
        *reinterpret_cast<float2*>(tp) = make_float2(h0, h1);
    }
}

// ---------------------------------------------------------------------------
extern "C" void kernel_launch(void* const* d_in, const int* in_sizes, int n_in,
                              void* d_out, int out_size)
{
    const float* input = (const float*)d_in[0];
    const float* W_in  = (const float*)d_in[1];
    const float* W_hid = (const float*)d_in[2];
    const float* noise = (const float*)d_in[3];
    float* out = (float*)d_out;

    cudaFuncSetAttribute(recurrent_kernel,
                         cudaFuncAttributeMaxDynamicSharedMemorySize, SMEM_BYTES);

    dim3 grid((SEQ * BATCH) / 64, HIDDEN / 64);
    proj_kernel<<<grid, 256>>>(input, W_in, out);

    int has_tail = (out_size >= SEQ * BATCH * HIDDEN + BATCH * HIDDEN) ? 1 : 0;
    recurrent_kernel<<<128, THREADS, SMEM_BYTES>>>(W_hid, noise, out, has_tail);
}

// round 7
// speedup vs baseline: 1.3714x; 1.3714x over previous
#include <cuda_runtime.h>
#include <cstdint>

typedef unsigned long long ull;

#define SEQ    512
#define BATCH  128
#define INPUT  128
#define HIDDEN 512
#define CLUSTER 8
#define THREADS 512

// ---- recurrent smem layout (bytes) ----
// W slice [512 k][64 n] fp32                         131072
// h buffers: [engine 2][parity 2][k 512][b 4] f32x2   65536 (16384 each)
// scr partials: [engine 2][kq 8][b 4][n 64] fp32      16384
// mbarriers: [engine 2][parity 2]                        32
#define HB_OFF   131072
#define SCR_OFF  196608
#define MB_OFF   212992
#define SMEM_BYTES 213056
#define EXCH_BYTES 16384u   // per engine per step: 8 CTAs x 256 thr x 8B

// ---------------------------------------------------------------------------
// Phase 1: proj[row,n] = sum_k input[row,k] * W_in[n,k] -> d_out
// ---------------------------------------------------------------------------
__global__ __launch_bounds__(256) void proj_kernel(
    const float* __restrict__ A, const float* __restrict__ W,
    float* __restrict__ C)
{
    __shared__ float As[64][65];
    __shared__ float Bs[64][65];
    const int tid = threadIdx.x, tx = tid & 15, ty = tid >> 4;
    const int row0 = blockIdx.x * 64, n0 = blockIdx.y * 64;
    float acc[4][4] = {};
    for (int k0 = 0; k0 < INPUT; k0 += 64) {
        #pragma unroll
        for (int i = 0; i < 16; i++) {
            int e = tid + i * 256, r = e >> 6, kk = e & 63;
            As[kk][r] = A[(row0 + r) * INPUT + k0 + kk];
            Bs[kk][r] = W[(n0 + r) * INPUT + k0 + kk];
        }
        __syncthreads();
        #pragma unroll 8
        for (int k = 0; k < 64; k++) {
            float a[4], b[4];
            #pragma unroll
            for (int i = 0; i < 4; i++) a[i] = As[k][ty * 4 + i];
            #pragma unroll
            for (int j = 0; j < 4; j++) b[j] = Bs[k][tx * 4 + j];
            #pragma unroll
            for (int i = 0; i < 4; i++)
                #pragma unroll
                for (int j = 0; j < 4; j++) acc[i][j] += a[i] * b[j];
        }
        __syncthreads();
    }
    #pragma unroll
    for (int i = 0; i < 4; i++) {
        int row = row0 + ty * 4 + i;
        #pragma unroll
        for (int j = 0; j < 4; j++)
            C[row * HIDDEN + n0 + tx * 4 + j] = acc[i][j];
    }
}

// ---- helpers ---------------------------------------------------------------
__device__ __forceinline__ void fma2(ull& d, ull a, ull b) {
    asm("fma.rn.f32x2 %0, %1, %2, %0;" : "+l"(d) : "l"(a), "l"(b));
}
__device__ __forceinline__ ull pk(float lo, float hi) {
    ull d; asm("mov.b64 %0, {%1, %2};" : "=l"(d) : "f"(lo), "f"(hi)); return d;
}
__device__ __forceinline__ uint32_t s2u(const void* p) {
    uint32_t a;
    asm("{ .reg .u64 t; cvta.to.shared.u64 t, %1; cvt.u32.u64 %0, t; }" : "=r"(a) : "l"(p));
    return a;
}

#define MB_WAIT(mb, ph) do {                                                    \
    uint32_t _done;                                                             \
    asm volatile("{\n\t.reg .pred p;\n\t"                                       \
        "mbarrier.try_wait.parity.acquire.cluster.shared::cta.b64 p, [%1], %2;\n\t" \
        "selp.b32 %0, 1, 0, p;\n\t}"                                            \
        : "=r"(_done) : "r"(mb), "r"(ph) : "memory");                           \
    while (!_done) {                                                            \
        asm volatile("{\n\t.reg .pred p;\n\t"                                   \
            "mbarrier.try_wait.parity.acquire.cluster.shared::cta.b64 p, [%1], %2, 0x989680;\n\t" \
            "selp.b32 %0, 1, 0, p;\n\t}"                                        \
            : "=r"(_done) : "r"(mb), "r"(ph) : "memory");                       \
    }                                                                           \
} while (0)

#define MB_ARM(mb)                                                              \
    asm volatile("mbarrier.arrive.expect_tx.shared.b64 _, [%0], %1;"            \
                 :: "r"(mb), "r"(EXCH_BYTES) : "memory")

#define ST_ASYNC64(dst, val, mb)                                                \
    asm volatile("st.async.weak.shared::cluster.mbarrier::complete_tx::bytes.b64 [%0], %1, [%2];" \
                 :: "r"(dst), "l"(val), "r"(mb) : "memory")

// ---------------------------------------------------------------------------
// Phase 2: persistent cluster recurrence, dual warp-specialized engines.
//   16 clusters x 8 CTAs; rank owns 64 hidden cols (W slice smem-resident).
//   Engine e (warps 8e..8e+7) runs an independent 4-batch-row chain.
//   Exchange: fire-and-forget st.async of dup'd relu(h) pairs into every
//   rank's matvec-ready buffer; receiver mbarrier counts 16KB tx. No cluster
//   barrier, no store drain, no dup pass.
// ---------------------------------------------------------------------------
__global__ void __launch_bounds__(THREADS, 1) __cluster_dims__(CLUSTER, 1, 1)
recurrent_kernel(const float* __restrict__ Whid,
                 const float* __restrict__ noise,
                 float* __restrict__ out, int has_tail)
{
    extern __shared__ float sm[];
    const uint32_t sbase = s2u(sm);

    const int tid = threadIdx.x;
    uint32_t rank;
    asm("mov.u32 %0, %%cluster_ctarank;" : "=r"(rank));
    const int n0r   = (int)rank * 64;
    const int bbase = (blockIdx.x >> 3) * 8;

    // ---- load W slice transposed: Ws[k*64+n] = Whid[n0r+n][k] ----
    for (int e2 = tid; e2 < 64 * 128; e2 += THREADS) {
        int n = e2 >> 7, kq4 = e2 & 127;
        float4 v = reinterpret_cast<const float4*>(Whid)[(n0r + n) * 128 + kq4];
        sm[(4 * kq4 + 0) * 64 + n] = v.x;
        sm[(4 * kq4 + 1) * 64 + n] = v.y;
        sm[(4 * kq4 + 2) * 64 + n] = v.z;
        sm[(4 * kq4 + 3) * 64 + n] = v.w;
    }
    // ---- zero parity-0 h buffers (h0 = 0 -> relu = 0) for both engines ----
    for (int i = tid; i < 4096; i += THREADS) {
        sm[HB_OFF / 4 + i]        = 0.0f;   // engine 0, parity 0
        sm[HB_OFF / 4 + 8192 + i] = 0.0f;   // engine 1, parity 0
    }
    // ---- init + pre-arm all 4 mbarriers ----
    if (tid == 0) {
        #pragma unroll
        for (int m = 0; m < 4; m++) {
            uint32_t mb = sbase + MB_OFF + m * 8;
            asm volatile("mbarrier.init.shared.b64 [%0], %1;" :: "r"(mb), "r"(1u) : "memory");
        }
        asm volatile("fence.proxy.async.shared::cta;" ::: "memory");
        #pragma unroll
        for (int m = 0; m < 4; m++) MB_ARM(sbase + MB_OFF + m * 8);
    }
    __syncthreads();
    asm volatile("barrier.cluster.arrive.aligned;" ::: "memory");
    asm volatile("barrier.cluster.wait.aligned;"   ::: "memory");

    // ---- engine / thread mapping ----
    const int e    = tid >> 8;           // engine 0/1 (warps 0-7 / 8-15)
    const int etid = tid & 255;
    // matvec: kq (8 x 64k) x bg (2 x 2b) x ng (16 x 4n)
    const int kq = etid >> 5;
    const int ng = etid & 15;
    const int bg = (etid >> 4) & 1;
    const uint32_t wp0 = sbase + (uint32_t)(kq * 16384 + ng * 16);
    // reduce/epilogue: one output (b, col) per thread
    const int rb   = etid >> 6;          // 0..3
    const int rn   = etid & 63;
    const int col  = n0r + rn;
    const int gb   = bbase + e * 4 + rb; // global batch row
    const uint32_t scr_st = sbase + SCR_OFF + (uint32_t)((e * 2048 + kq * 256 + 2 * bg * 64 + 4 * ng) * 4);
    const uint32_t scr_rd = sbase + SCR_OFF + (uint32_t)((e * 2048 + rb * 64 + rn) * 4);
    const uint32_t mb0 = sbase + MB_OFF + (uint32_t)(e * 16);        // parity 0
    const uint32_t mb1 = mb0 + 8;                                    // parity 1
    const uint32_t hb0 = sbase + HB_OFF + (uint32_t)(e * 32768);     // parity 0 buf
    // peer CTA smem bases
    uint32_t peer[CLUSTER];
    #pragma unroll
    for (int r = 0; r < CLUSTER; r++)
        asm("mapa.shared::cluster.u32 %0, %1, %2;" : "=r"(peer[r]) : "r"(sbase), "r"(r));
    const uint32_t slot = (uint32_t)((col * 4 + rb) * 8);            // within a buffer
    const uint32_t hboff0 = (uint32_t)(HB_OFF + e * 32768);
    const uint32_t mboff0 = (uint32_t)(MB_OFF + e * 16);

    float rh = 0.0f;
    int ph0 = 0, ph1 = 0;

    for (int s = 0; s < SEQ; s++) {
        const int ibuf = s & 1;
        if (s > 0) {
            uint32_t mb = ibuf ? mb1 : mb0;
            int& ph = ibuf ? ph1 : ph0;
            MB_WAIT(mb, ph);
            if (etid == 0) MB_ARM(mb);   // re-arm for step s+2
            ph ^= 1;
        }
        // prefetch proj (in d_out) + noise for the epilogue
        float* optr = out + ((size_t)s * BATCH + gb) * HIDDEN + col;
        float x  = *optr;
        float nz = __ldg(&noise[(size_t)s * HIDDEN + col]);

        // ---- matvec over this thread's 64-k slice ----
        const uint32_t hp0 = hb0 + (uint32_t)(ibuf * 16384 + kq * 2048 + bg * 16);
        ull a00 = 0, a01 = 0, a10 = 0, a11 = 0;
        #pragma unroll 8
        for (int k = 0; k < 64; k++) {
            ull w01, w23, h0, h1;
            asm("ld.shared.v2.u64 {%0,%1}, [%2];"
                : "=l"(w01), "=l"(w23) : "r"(wp0 + (uint32_t)(k * 256)));
            asm("ld.shared.v2.u64 {%0,%1}, [%2];"
                : "=l"(h0), "=l"(h1) : "r"(hp0 + (uint32_t)(k * 32)));
            fma2(a00, h0, w01); fma2(a01, h0, w23);
            fma2(a10, h1, w01); fma2(a11, h1, w23);
        }
        // partials: b=2bg at +0, b=2bg+1 at +256 bytes (one 64-float b-row)
        asm volatile("st.shared.v2.u64 [%0],     {%1,%2};" :: "r"(scr_st), "l"(a00), "l"(a01));
        asm volatile("st.shared.v2.u64 [%0+256], {%1,%2};" :: "r"(scr_st), "l"(a10), "l"(a11));

        // engine-local barrier: matvec partials visible
        asm volatile("bar.sync %0, 256;" :: "r"(1 + e) : "memory");

        // ---- reduce 8 k-partials + state update ----
        float acc = 0.0f;
        #pragma unroll
        for (int q = 0; q < 8; q++) {
            float v;
            asm("ld.shared.f32 %0, [%1];" : "=f"(v) : "r"(scr_rd + (uint32_t)(q * 1024)));
            acc += v;
        }
        float hn = 0.5f * rh + 0.5f * (acc + x + nz);
        rh = hn;
        *optr = hn;

        // ---- fire-and-forget exchange of dup'd relu(h_new) ----
        if (s < SEQ - 1) {
            float rv = fmaxf(hn, 0.0f);
            ull pr = pk(rv, rv);
            uint32_t boff = hboff0 + (uint32_t)((ibuf ^ 1) * 16384) + slot;
            uint32_t moff = mboff0 + (uint32_t)((ibuf ^ 1) * 8);
            #pragma unroll
            for (int r = 0; r < CLUSTER; r++)
                ST_ASYNC64(peer[r] + boff, pr, peer[r] + moff);
        }
    }

    // ---- fused tail: final hidden state ----
    if (has_tail)
        out[(size_t)SEQ * BATCH * HIDDEN + (size_t)gb * HIDDEN + col] = rh;

    // keep smem alive until all cluster peers are done storing
    asm volatile("barrier.cluster.arrive.aligned;" ::: "memory");
    asm volatile("barrier.cluster.wait.aligned;"   ::: "memory");
}

// ---------------------------------------------------------------------------
extern "C" void kernel_launch(void* const* d_in, const int* in_sizes, int n_in,
                              void* d_out, int out_size)
{
    const float* input = (const float*)d_in[0];
    const float* W_in  = (const float*)d_in[1];
    const float* W_hid = (const float*)d_in[2];
    const float* noise = (const float*)d_in[3];
    float* out = (float*)d_out;

    cudaFuncSetAttribute(recurrent_kernel,
                         cudaFuncAttributeMaxDynamicSharedMemorySize, SMEM_BYTES);

    dim3 grid((SEQ * BATCH) / 64, HIDDEN / 64);
    proj_kernel<<<grid, 256>>>(input, W_in, out);

    int has_tail = (out_size >= SEQ * BATCH * HIDDEN + BATCH * HIDDEN) ? 1 : 0;
    recurrent_kernel<<<128, THREADS, SMEM_BYTES>>>(W_hid, noise, out, has_tail);
}

// round 8
// speedup vs baseline: 2.5037x; 1.8256x over previous
#include <cuda_runtime.h>
#include <cstdint>

typedef unsigned long long ull;

#define SEQ    512
#define BATCH  128
#define INPUT  128
#define HIDDEN 512
#define CLUSTER 8
#define THREADS 512

// ---- recurrent smem layout (bytes) ----
// W slice  [512 k][64 n] fp32                          131072
// hc compact h: [e 2][par 2][k 512][b 4] fp32           32768 (8192 each)
// staging:  [e 2][par 2][256 vals] fp32                  4096
// scr partials: [e 2][kq 8][b 4][n 64] fp32             16384
// mbarriers: [e 2][par 2] x 8B                              32
#define HC_OFF   131072
#define STG_OFF  163840
#define SCR_OFF  167936
#define MB_OFF   184320
#define SMEM_BYTES 184384
#define EXCH_BYTES 8192u     // per engine per step: 8 ranks x 1KB

// ---------------------------------------------------------------------------
// Phase 1: proj[row,n] = sum_k input[row,k] * W_in[n,k] -> d_out
// ---------------------------------------------------------------------------
__global__ __launch_bounds__(256) void proj_kernel(
    const float* __restrict__ A, const float* __restrict__ W,
    float* __restrict__ C)
{
    __shared__ float As[64][65];
    __shared__ float Bs[64][65];
    const int tid = threadIdx.x, tx = tid & 15, ty = tid >> 4;
    const int row0 = blockIdx.x * 64, n0 = blockIdx.y * 64;
    float acc[4][4] = {};
    for (int k0 = 0; k0 < INPUT; k0 += 64) {
        #pragma unroll
        for (int i = 0; i < 16; i++) {
            int e = tid + i * 256, r = e >> 6, kk = e & 63;
            As[kk][r] = A[(row0 + r) * INPUT + k0 + kk];
            Bs[kk][r] = W[(n0 + r) * INPUT + k0 + kk];
        }
        __syncthreads();
        #pragma unroll 8
        for (int k = 0; k < 64; k++) {
            float a[4], b[4];
            #pragma unroll
            for (int i = 0; i < 4; i++) a[i] = As[k][ty * 4 + i];
            #pragma unroll
            for (int j = 0; j < 4; j++) b[j] = Bs[k][tx * 4 + j];
            #pragma unroll
            for (int i = 0; i < 4; i++)
                #pragma unroll
                for (int j = 0; j < 4; j++) acc[i][j] += a[i] * b[j];
        }
        __syncthreads();
    }
    #pragma unroll
    for (int i = 0; i < 4; i++) {
        int row = row0 + ty * 4 + i;
        #pragma unroll
        for (int j = 0; j < 4; j++)
            C[row * HIDDEN + n0 + tx * 4 + j] = acc[i][j];
    }
}

// ---- helpers ---------------------------------------------------------------
__device__ __forceinline__ void fma2(ull& d, ull a, ull b) {
    asm("fma.rn.f32x2 %0, %1, %2, %0;" : "+l"(d) : "l"(a), "l"(b));
}
__device__ __forceinline__ ull pk(float lo, float hi) {
    ull d; asm("mov.b64 %0, {%1, %2};" : "=l"(d) : "f"(lo), "f"(hi)); return d;
}
__device__ __forceinline__ uint32_t s2u(const void* p) {
    uint32_t a;
    asm("{ .reg .u64 t; cvta.to.shared.u64 t, %1; cvt.u32.u64 %0, t; }" : "=r"(a) : "l"(p));
    return a;
}

#define MB_WAIT(mb, ph) do {                                                    \
    uint32_t _done;                                                             \
    asm volatile("{\n\t.reg .pred p;\n\t"                                       \
        "mbarrier.try_wait.parity.acquire.cluster.shared::cta.b64 p, [%1], %2;\n\t" \
        "selp.b32 %0, 1, 0, p;\n\t}"                                            \
        : "=r"(_done) : "r"(mb), "r"(ph) : "memory");                           \
    while (!_done) {                                                            \
        asm volatile("{\n\t.reg .pred p;\n\t"                                   \
            "mbarrier.try_wait.parity.acquire.cluster.shared::cta.b64 p, [%1], %2, 0x989680;\n\t" \
            "selp.b32 %0, 1, 0, p;\n\t}"                                        \
            : "=r"(_done) : "r"(mb), "r"(ph) : "memory");                       \
    }                                                                           \
} while (0)

#define MB_ARM(mb)                                                              \
    asm volatile("mbarrier.arrive.expect_tx.shared.b64 _, [%0], %1;"            \
                 :: "r"(mb), "r"(EXCH_BYTES) : "memory")

// bulk smem->peer-smem copy, tx-counted at the peer's mbarrier
#define BULK_CLUSTER(dst, src, bytes, mb)                                       \
    asm volatile("cp.async.bulk.shared::cluster.shared::cta.mbarrier::complete_tx::bytes " \
                 "[%0], [%1], %2, [%3];"                                        \
                 :: "r"(dst), "r"(src), "r"(bytes), "r"(mb) : "memory")

// ---------------------------------------------------------------------------
// Phase 2: persistent cluster recurrence, dual warp-specialized engines.
//   16 clusters x 8 CTAs; rank owns 64 hidden cols (W slice smem-resident).
//   Engine e (warps 8e..8e+7) runs an independent 4-batch-row chain.
//   Exchange: epilogue stages 1KB of compact relu(h) locally, then ONE thread
//   issues 8 cp.async.bulk copies (one per peer) -> 8 transactions/step
//   instead of 2048 scalar messages. Receiver mbar tx-counts 8KB.
// ---------------------------------------------------------------------------
__global__ void __launch_bounds__(THREADS, 1) __cluster_dims__(CLUSTER, 1, 1)
recurrent_kernel(const float* __restrict__ Whid,
                 const float* __restrict__ noise,
                 float* __restrict__ out, int has_tail)
{
    extern __shared__ float sm[];
    const uint32_t sbase = s2u(sm);

    const int tid = threadIdx.x;
    uint32_t rank;
    asm("mov.u32 %0, %%cluster_ctarank;" : "=r"(rank));
    const int n0r   = (int)rank * 64;
    const int bbase = (blockIdx.x >> 3) * 8;

    // ---- load W slice transposed: Ws[k*64+n] = Whid[n0r+n][k] ----
    for (int e2 = tid; e2 < 64 * 128; e2 += THREADS) {
        int n = e2 >> 7, kq4 = e2 & 127;
        float4 v = reinterpret_cast<const float4*>(Whid)[(n0r + n) * 128 + kq4];
        sm[(4 * kq4 + 0) * 64 + n] = v.x;
        sm[(4 * kq4 + 1) * 64 + n] = v.y;
        sm[(4 * kq4 + 2) * 64 + n] = v.z;
        sm[(4 * kq4 + 3) * 64 + n] = v.w;
    }
    // ---- zero parity-0 compact h buffers (h0 = 0 -> relu = 0) ----
    for (int i = tid; i < 2048; i += THREADS) {
        sm[HC_OFF / 4 + i]        = 0.0f;   // engine 0, parity 0
        sm[HC_OFF / 4 + 4096 + i] = 0.0f;   // engine 1, parity 0
    }
    // ---- init + pre-arm all 4 mbarriers ----
    if (tid == 0) {
        #pragma unroll
        for (int m = 0; m < 4; m++) {
            uint32_t mb = sbase + MB_OFF + m * 8;
            asm volatile("mbarrier.init.shared.b64 [%0], %1;" :: "r"(mb), "r"(1u) : "memory");
        }
        asm volatile("fence.proxy.async.shared::cta;" ::: "memory");
        #pragma unroll
        for (int m = 0; m < 4; m++) MB_ARM(sbase + MB_OFF + m * 8);
    }
    __syncthreads();
    asm volatile("barrier.cluster.arrive.aligned;" ::: "memory");
    asm volatile("barrier.cluster.wait.aligned;"   ::: "memory");

    // ---- engine / thread mapping ----
    const int e    = tid >> 8;           // engine 0/1
    const int etid = tid & 255;
    // matvec: kq (8 x 64k) x bg (2 x 2b) x ng (16 x 4n)
    const int kq = etid >> 5;
    const int ng = etid & 15;
    const int bg = (etid >> 4) & 1;
    const uint32_t wp0 = sbase + (uint32_t)(kq * 16384 + ng * 16);
    // reduce/epilogue: one output (b, col) per thread
    const int rb   = etid >> 6;          // 0..3
    const int rn   = etid & 63;
    const int col  = n0r + rn;
    const int gb   = bbase + e * 4 + rb; // global batch row
    const uint32_t scr_st = sbase + SCR_OFF + (uint32_t)((e * 2048 + kq * 256 + 2 * bg * 64 + 4 * ng) * 4);
    const uint32_t scr_rd = sbase + SCR_OFF + (uint32_t)((e * 2048 + rb * 64 + rn) * 4);
    const uint32_t mb0 = sbase + MB_OFF + (uint32_t)(e * 16);        // parity 0
    const uint32_t mb1 = mb0 + 8;                                    // parity 1
    const uint32_t hcb = sbase + HC_OFF + (uint32_t)(e * 16384);     // this engine's buffers
    // peer CTA smem bases
    uint32_t peer[CLUSTER];
    #pragma unroll
    for (int r = 0; r < CLUSTER; r++)
        asm("mapa.shared::cluster.u32 %0, %1, %2;" : "=r"(peer[r]) : "r"(sbase), "r"(r));
    const uint32_t stg_base = sbase + STG_OFF + (uint32_t)(e * 2048);
    const uint32_t stg_slot = (uint32_t)((rn * 4 + rb) * 4);  // [n][b] matches [k][b] rows

    float rh = 0.0f;
    int ph0 = 0, ph1 = 0;

    for (int s = 0; s < SEQ; s++) {
        const int ibuf = s & 1;
        if (s > 0) {
            uint32_t mb = ibuf ? mb1 : mb0;
            int& ph = ibuf ? ph1 : ph0;
            MB_WAIT(mb, ph);
            if (etid == 0) MB_ARM(mb);   // re-arm for step s+2
            ph ^= 1;
        }
        // prefetch proj (in d_out) + noise for the epilogue
        float* optr = out + ((size_t)s * BATCH + gb) * HIDDEN + col;
        float x  = *optr;
        float nz = __ldg(&noise[(size_t)s * HIDDEN + col]);

        // ---- matvec over this thread's 64-k slice (compact h, reg dup) ----
        const uint32_t hp0 = hcb + (uint32_t)(ibuf * 8192 + kq * 1024 + bg * 8);
        ull a00 = 0, a01 = 0, a10 = 0, a11 = 0;
        #pragma unroll 8
        for (int k = 0; k < 64; k++) {
            ull w01, w23;
            float hx, hy;
            asm("ld.shared.v2.u64 {%0,%1}, [%2];"
                : "=l"(w01), "=l"(w23) : "r"(wp0 + (uint32_t)(k * 256)));
            asm("ld.shared.v2.f32 {%0,%1}, [%2];"
                : "=f"(hx), "=f"(hy) : "r"(hp0 + (uint32_t)(k * 16)));
            ull h0 = pk(hx, hx), h1 = pk(hy, hy);
            fma2(a00, h0, w01); fma2(a01, h0, w23);
            fma2(a10, h1, w01); fma2(a11, h1, w23);
        }
        // partials: b=2bg at +0, b=2bg+1 at +256 bytes
        asm volatile("st.shared.v2.u64 [%0],     {%1,%2};" :: "r"(scr_st), "l"(a00), "l"(a01));
        asm volatile("st.shared.v2.u64 [%0+256], {%1,%2};" :: "r"(scr_st), "l"(a10), "l"(a11));

        // engine barrier #1: matvec partials visible
        asm volatile("bar.sync %0, 256;" :: "r"(1 + e) : "memory");

        // ---- reduce 8 k-partials + state update ----
        float acc = 0.0f;
        #pragma unroll
        for (int q = 0; q < 8; q++) {
            float v;
            asm("ld.shared.f32 %0, [%1];" : "=f"(v) : "r"(scr_rd + (uint32_t)(q * 1024)));
            acc += v;
        }
        float hn = 0.5f * rh + 0.5f * (acc + x + nz);
        rh = hn;
        *optr = hn;

        if (s < SEQ - 1) {
            // stage compact relu(h_new) locally (parity of NEXT step)
            float rv = fmaxf(hn, 0.0f);
            uint32_t stg = stg_base + (uint32_t)((ibuf ^ 1) * 1024) + stg_slot;
            asm volatile("st.shared.f32 [%0], %1;" :: "r"(stg), "f"(rv) : "memory");

            // engine barrier #2: staging complete (also protects scr/hc WAR)
            asm volatile("bar.sync %0, 256;" :: "r"(1 + e) : "memory");

            // ---- ONE thread issues 8 bulk copies (1KB each) ----
            if (etid == 0) {
                asm volatile("fence.proxy.async.shared::cta;" ::: "memory");
                uint32_t src    = stg_base + (uint32_t)((ibuf ^ 1) * 1024);
                uint32_t dstoff = (uint32_t)(HC_OFF + e * 16384 + (ibuf ^ 1) * 8192
                                             + (int)rank * 1024);
                uint32_t mboff  = (uint32_t)(MB_OFF + e * 16 + (ibuf ^ 1) * 8);
                #pragma unroll
                for (int r = 0; r < CLUSTER; r++)
                    BULK_CLUSTER(peer[r] + dstoff, src, 1024u, peer[r] + mboff);
            }
        }
    }

    // ---- fused tail: final hidden state ----
    if (has_tail)
        out[(size_t)SEQ * BATCH * HIDDEN + (size_t)gb * HIDDEN + col] = rh;

    // keep smem alive until all cluster peers are done
    asm volatile("barrier.cluster.arrive.aligned;" ::: "memory");
    asm volatile("barrier.cluster.wait.aligned;"   ::: "memory");
}

// ---------------------------------------------------------------------------
extern "C" void kernel_launch(void* const* d_in, const int* in_sizes, int n_in,
                              void* d_out, int out_size)
{
    const float* input = (const float*)d_in[0];
    const float* W_in  = (const float*)d_in[1];
    const float* W_hid = (const float*)d_in[2];
    const float* noise = (const float*)d_in[3];
    float* out = (float*)d_out;

    cudaFuncSetAttribute(recurrent_kernel,
                         cudaFuncAttributeMaxDynamicSharedMemorySize, SMEM_BYTES);

    dim3 grid((SEQ * BATCH) / 64, HIDDEN / 64);
    proj_kernel<<<grid, 256>>>(input, W_in, out);

    int has_tail = (out_size >= SEQ * BATCH * HIDDEN + BATCH * HIDDEN) ? 1 : 0;
    recurrent_kernel<<<128, THREADS, SMEM_BYTES>>>(W_hid, noise, out, has_tail);
}